// round 15
// baseline (speedup 1.0000x reference)
#include <cuda_runtime.h>
#include <math.h>

#define NN   50000
#define E0   800000
#define ETOT 850000
#define F1   256          // heads*HID  (layer-1 concat width)
#define F2   512          // heads*OUT  (layer-2 pre-mean width)
#define NT   49           // scan tiles of 1024

// ---------------- scratch (device globals; no allocations) ----------------
__device__ float g_h1[(size_t)NN * F1];    // layer1 pre-attn features
__device__ float g_hr[(size_t)NN * F1];    // layer1 post-attn relu output (tf32-rounded)
__device__ float g_h2[(size_t)NN * F2];    // layer2 pre-attn features
__device__ float g_xr[(size_t)NN * 128];   // tf32-rounded x
__device__ float g_w1r[128 * F1];          // tf32-rounded W1
__device__ float g_w2r[F1 * F2];           // tf32-rounded W2
__device__ float g_es[NN * 4];             // e_src per node/head
__device__ float g_ed[NN * 4];             // e_dst per node/head
__device__ int   g_deg[NN];
__device__ int   g_rowptr[NN + 1];
__device__ int   g_pos[NN];
__device__ int   g_srcs[ETOT];
__device__ int   g_part[64];
__device__ int   g_partoff[64];
__device__ int   g_is64;

// ---------------- helpers ----------------
__device__ __forceinline__ unsigned f2tf32(float f) {
    unsigned r;
    asm("cvt.rna.tf32.f32 %0, %1;" : "=r"(r) : "f"(f));
    return r;
}
__device__ __forceinline__ float roundtf(float f) { return __uint_as_float(f2tf32(f)); }

__device__ __forceinline__ void edge_nodes(const void* __restrict__ ei, int e,
                                           int& src, int& dst) {
    if (e >= E0) { src = dst = e - E0; return; }
    if (g_is64) {
        const long long* p = (const long long*)ei;
        src = (int)p[e];
        dst = (int)p[E0 + e];
    } else {
        const int* p = (const int*)ei;
        src = p[e];
        dst = p[E0 + e];
    }
}

__global__ void detect_idx_kernel(const int* __restrict__ ei32) {
    if (threadIdx.x == 0) {
        int all0 = 1;
        for (int i = 1; i < 256; i += 2) all0 &= (ei32[i] == 0);
        g_is64 = all0;
    }
}

// round a float buffer to tf32 (RN) into dst
__global__ void round_copy(const float* __restrict__ src, float* __restrict__ dst,
                           size_t n4) {
    size_t i  = (size_t)blockIdx.x * blockDim.x + threadIdx.x;
    size_t st = (size_t)gridDim.x * blockDim.x;
    const float4* s4 = reinterpret_cast<const float4*>(src);
    float4* d4 = reinterpret_cast<float4*>(dst);
    for (size_t j = i; j < n4; j += st) {
        float4 v = s4[j];
        v.x = roundtf(v.x); v.y = roundtf(v.y);
        v.z = roundtf(v.z); v.w = roundtf(v.w);
        d4[j] = v;
    }
}

// ---------------- CSR build ----------------
__global__ void zero_deg() {
    int i = blockIdx.x * blockDim.x + threadIdx.x;
    if (i < NN) g_deg[i] = 0;
}

__global__ void hist_kernel(const void* __restrict__ ei) {
    int e = blockIdx.x * blockDim.x + threadIdx.x;
    if (e >= ETOT) return;
    int src, dst;
    edge_nodes(ei, e, src, dst);
    atomicAdd(&g_deg[dst], 1);
}

__global__ void scan_tiles() {
    __shared__ int warpsum[32];
    int tid = threadIdx.x;
    int i = blockIdx.x * 1024 + tid;
    int lane = tid & 31, wid = tid >> 5;
    int v = (i < NN) ? g_deg[i] : 0;
    int s = v;
#pragma unroll
    for (int off = 1; off < 32; off <<= 1) {
        int t = __shfl_up_sync(0xffffffffu, s, off);
        if (lane >= off) s += t;
    }
    if (lane == 31) warpsum[wid] = s;
    __syncthreads();
    if (wid == 0) {
        int ws = warpsum[lane];
#pragma unroll
        for (int off = 1; off < 32; off <<= 1) {
            int t = __shfl_up_sync(0xffffffffu, ws, off);
            if (lane >= off) ws += t;
        }
        warpsum[lane] = ws;
    }
    __syncthreads();
    int excl = s - v + (wid > 0 ? warpsum[wid - 1] : 0);
    if (i < NN) g_rowptr[i] = excl;
    if (tid == 0) g_part[blockIdx.x] = warpsum[31];
}

__global__ void scan_parts() {
    __shared__ int sp[64];
    int tid = threadIdx.x;
    int v = (tid < NT) ? g_part[tid] : 0;
    sp[tid] = v;
    __syncthreads();
#pragma unroll
    for (int off = 1; off < 64; off <<= 1) {
        int t = sp[tid];
        int add = (tid >= off) ? sp[tid - off] : 0;
        __syncthreads();
        sp[tid] = t + add;
        __syncthreads();
    }
    g_partoff[tid] = sp[tid] - v;
}

__global__ void add_offsets() {
    int i = blockIdx.x * 1024 + threadIdx.x;
    if (i < NN) {
        int r = g_rowptr[i] + g_partoff[blockIdx.x];
        g_rowptr[i] = r;
        g_pos[i]    = r;
    }
    if (i == 0) g_rowptr[NN] = ETOT;
}

__global__ void scatter_kernel(const void* __restrict__ ei) {
    int e = blockIdx.x * blockDim.x + threadIdx.x;
    if (e >= ETOT) return;
    int src, dst;
    edge_nodes(ei, e, src, dst);
    int p = atomicAdd(&g_pos[dst], 1);
    g_srcs[p] = src;
}

// ---------------- tf32 GEMM, 128x128 tile, cp.async 2-stage, fused attn scores ----
// Inputs A,B must be pre-rounded to tf32 (low 13 bits zero) -> raw bit reinterpret == RN.
__device__ __forceinline__ void mma_tf32(float* d, const unsigned* a, const unsigned* b) {
    asm volatile(
        "mma.sync.aligned.m16n8k8.row.col.f32.tf32.tf32.f32 "
        "{%0,%1,%2,%3}, {%4,%5,%6,%7}, {%8,%9}, {%0,%1,%2,%3};"
        : "+f"(d[0]), "+f"(d[1]), "+f"(d[2]), "+f"(d[3])
        : "r"(a[0]), "r"(a[1]), "r"(a[2]), "r"(a[3]), "r"(b[0]), "r"(b[1]));
}
__device__ __forceinline__ void cp_async16(unsigned saddr, const void* gaddr, int srcb) {
    asm volatile("cp.async.ca.shared.global [%0], [%1], 16, %2;"
                 :: "r"(saddr), "l"(gaddr), "r"(srcb));
}

#define AS_STRIDE 36
#define BS_STRIDE 136
#define AS_ELEMS  (128 * AS_STRIDE)
#define BS_ELEMS  (32 * BS_STRIDE)
#define GEMM_SMEM ((2 * AS_ELEMS + 2 * BS_ELEMS) * 4)   // 71680 B

// CH = per-head channel count for fused attention scores.
template <int CH>
__global__ __launch_bounds__(256) void gemm_db(const float* __restrict__ A,
                                               const float* __restrict__ B,
                                               float* __restrict__ C,
                                               int n, int K, int J,
                                               const float* __restrict__ a_src,
                                               const float* __restrict__ a_dst,
                                               float* __restrict__ es,
                                               float* __restrict__ ed) {
    extern __shared__ float sm[];
    float* As = sm;
    float* Bs = sm + 2 * AS_ELEMS;
    int tid  = threadIdx.x;
    int warp = tid >> 5, lane = tid & 31;
    int wm = (warp & 3) * 32;
    int wn = (warp >> 2) * 64;
    int row0 = blockIdx.y * 128;
    int col0 = blockIdx.x * 128;
    int lr = lane >> 2, lc = lane & 3;

    unsigned as_base = (unsigned)__cvta_generic_to_shared(As);
    unsigned bs_base = (unsigned)__cvta_generic_to_shared(Bs);

    float acc[2][8][4];
#pragma unroll
    for (int i = 0; i < 2; i++)
#pragma unroll
        for (int j = 0; j < 8; j++)
#pragma unroll
            for (int q = 0; q < 4; q++) acc[i][j][q] = 0.f;

    auto issue = [&](int st, int k0) {
#pragma unroll
        for (int q = 0; q < 4; q++) {
            int c = tid + q * 256;
            int ar = c >> 3, kc = (c & 7) * 4;
            int grow = row0 + ar;
            unsigned dst = as_base + (st * AS_ELEMS + ar * AS_STRIDE + kc) * 4;
            const float* src = A + (size_t)grow * K + k0 + kc;
            cp_async16(dst, src, (grow < n) ? 16 : 0);
        }
#pragma unroll
        for (int q = 0; q < 4; q++) {
            int c = tid + q * 256;
            int br = c >> 5, bc = (c & 31) * 4;
            unsigned dst = bs_base + (st * BS_ELEMS + br * BS_STRIDE + bc) * 4;
            const float* src = B + (size_t)(k0 + br) * J + col0 + bc;
            cp_async16(dst, src, 16);
        }
        asm volatile("cp.async.commit_group;");
    };

    issue(0, 0);
    int st = 0;
    for (int k0 = 0; k0 < K; k0 += 32, st ^= 1) {
        if (k0 + 32 < K) {
            issue(st ^ 1, k0 + 32);
            asm volatile("cp.async.wait_group 1;");
        } else {
            asm volatile("cp.async.wait_group 0;");
        }
        __syncthreads();
        const unsigned* as = reinterpret_cast<const unsigned*>(As + st * AS_ELEMS);
        const unsigned* bs = reinterpret_cast<const unsigned*>(Bs + st * BS_ELEMS);
#pragma unroll
        for (int kk = 0; kk < 32; kk += 8) {
            unsigned a[2][4], b[8][2];
#pragma unroll
            for (int mf = 0; mf < 2; mf++) {
                int r = wm + mf * 16 + lr;
                a[mf][0] = as[r * AS_STRIDE + kk + lc];
                a[mf][1] = as[(r + 8) * AS_STRIDE + kk + lc];
                a[mf][2] = as[r * AS_STRIDE + kk + lc + 4];
                a[mf][3] = as[(r + 8) * AS_STRIDE + kk + lc + 4];
            }
#pragma unroll
            for (int nf = 0; nf < 8; nf++) {
                int c = wn + nf * 8 + lr;
                b[nf][0] = bs[(kk + lc) * BS_STRIDE + c];
                b[nf][1] = bs[(kk + lc + 4) * BS_STRIDE + c];
            }
#pragma unroll
            for (int mf = 0; mf < 2; mf++)
#pragma unroll
                for (int nf = 0; nf < 8; nf++)
                    mma_tf32(acc[mf][nf], a[mf], b[nf]);
        }
        __syncthreads();
    }

    // ---- store C ----
#pragma unroll
    for (int mf = 0; mf < 2; mf++) {
#pragma unroll
        for (int nf = 0; nf < 8; nf++) {
            int r = row0 + wm + mf * 16 + lr;
            int c = col0 + wn + nf * 8 + 2 * lc;
            if (r < n) {
                C[(size_t)r * J + c]     = acc[mf][nf][0];
                C[(size_t)r * J + c + 1] = acc[mf][nf][1];
            }
            if (r + 8 < n) {
                C[(size_t)(r + 8) * J + c]     = acc[mf][nf][2];
                C[(size_t)(r + 8) * J + c + 1] = acc[mf][nf][3];
            }
        }
    }

    // ---- fused attention scores from accumulators ----
    if (CH > 0) {
        int head0 = (col0 + wn) / CH;
        float psrc[4] = {0.f, 0.f, 0.f, 0.f};
        float pdst[4] = {0.f, 0.f, 0.f, 0.f};
#pragma unroll
        for (int nf = 0; nf < 8; nf++) {
            int cin = (col0 + wn + nf * 8 + 2 * lc) % CH;
            float a0s = a_src[head0 * CH + cin], a1s = a_src[head0 * CH + cin + 1];
            float a0d = a_dst[head0 * CH + cin], a1d = a_dst[head0 * CH + cin + 1];
#pragma unroll
            for (int mf = 0; mf < 2; mf++) {
                psrc[mf * 2 + 0] += acc[mf][nf][0] * a0s + acc[mf][nf][1] * a1s;
                pdst[mf * 2 + 0] += acc[mf][nf][0] * a0d + acc[mf][nf][1] * a1d;
                psrc[mf * 2 + 1] += acc[mf][nf][2] * a0s + acc[mf][nf][3] * a1s;
                pdst[mf * 2 + 1] += acc[mf][nf][2] * a0d + acc[mf][nf][3] * a1d;
            }
        }
#pragma unroll
        for (int off = 1; off <= 2; off <<= 1) {
#pragma unroll
            for (int i = 0; i < 4; i++) {
                psrc[i] += __shfl_down_sync(0xffffffffu, psrc[i], off);
                pdst[i] += __shfl_down_sync(0xffffffffu, pdst[i], off);
            }
        }
        float* part = sm;
        if (lc == 0) {
            int nw = warp >> 2;
#pragma unroll
            for (int i = 0; i < 4; i++) {
                int row = wm + (i >> 1) * 16 + lr + (i & 1) * 8;
                part[(row * 2 + nw) * 2 + 0] = psrc[i];
                part[(row * 2 + nw) * 2 + 1] = pdst[i];
            }
        }
        __syncthreads();
        if (tid < 128) {
            int grow = row0 + tid;
            if (grow < n) {
                if (CH == 64) {
                    int h0 = col0 / 64;
                    es[grow * 4 + h0]     = part[(tid * 2 + 0) * 2 + 0];
                    ed[grow * 4 + h0]     = part[(tid * 2 + 0) * 2 + 1];
                    es[grow * 4 + h0 + 1] = part[(tid * 2 + 1) * 2 + 0];
                    ed[grow * 4 + h0 + 1] = part[(tid * 2 + 1) * 2 + 1];
                } else {
                    int h = col0 / 128;
                    es[grow * 4 + h] = part[(tid * 2 + 0) * 2 + 0] + part[(tid * 2 + 1) * 2 + 0];
                    ed[grow * 4 + h] = part[(tid * 2 + 0) * 2 + 1] + part[(tid * 2 + 1) * 2 + 1];
                }
            }
        }
    }
}

// ---------------- fused per-node GAT aggregation ----------------
__device__ __forceinline__ float4 expleaky4(float4 a, float4 b) {
    float4 v;
    v.x = a.x + b.x; v.x = v.x > 0.f ? v.x : 0.2f * v.x; v.x = __expf(v.x);
    v.y = a.y + b.y; v.y = v.y > 0.f ? v.y : 0.2f * v.y; v.y = __expf(v.y);
    v.z = a.z + b.z; v.z = v.z > 0.f ? v.z : 0.2f * v.z; v.z = __expf(v.z);
    v.w = a.w + b.w; v.w = v.w > 0.f ? v.w : 0.2f * v.w; v.w = __expf(v.w);
    return v;
}

#define CHUNK 64

// Layer 1: stores hr tf32-rounded (only consumer is GEMM2, which needs rounded input).
__global__ __launch_bounds__(128) void gat_agg1(
    const float* __restrict__ h, const float* __restrict__ es, const float* __restrict__ ed,
    const float* __restrict__ bias, float* __restrict__ out) {
    int n = blockIdx.x;
    int tid = threadIdx.x;
    int lane = tid & 31, wid = tid >> 5;
    int r0 = g_rowptr[n], r1 = g_rowptr[n + 1];
    int deg = r1 - r0;
    float4 edv = *reinterpret_cast<const float4*>(ed + n * 4);

    __shared__ float4 s_red[4];
    __shared__ int    s_src[CHUNK];
    __shared__ float4 s_w[CHUNK];

    const float* hp = h + tid * 2;

    float a0 = 0.f, a1 = 0.f;
    float4 dpart = make_float4(0.f, 0.f, 0.f, 0.f);
    for (int base = 0; base < deg; base += CHUNK) {
        int cn = deg - base; if (cn > CHUNK) cn = CHUNK;
        if (tid < cn) {
            int s = g_srcs[r0 + base + tid];
            float4 w = expleaky4(*reinterpret_cast<const float4*>(es + s * 4), edv);
            s_src[tid] = s;
            s_w[tid] = w;
            dpart.x += w.x; dpart.y += w.y; dpart.z += w.z; dpart.w += w.w;
        }
        __syncthreads();
        const float* wf = reinterpret_cast<const float*>(s_w);
        int j = 0;
        for (; j + 4 <= cn; j += 4) {
            int s0 = s_src[j + 0], s1 = s_src[j + 1];
            int s2 = s_src[j + 2], s3 = s_src[j + 3];
            float w0 = wf[(j + 0) * 4 + wid];
            float w1 = wf[(j + 1) * 4 + wid];
            float w2 = wf[(j + 2) * 4 + wid];
            float w3 = wf[(j + 3) * 4 + wid];
            float2 v0 = *reinterpret_cast<const float2*>(hp + (size_t)s0 * F1);
            float2 v1 = *reinterpret_cast<const float2*>(hp + (size_t)s1 * F1);
            float2 v2 = *reinterpret_cast<const float2*>(hp + (size_t)s2 * F1);
            float2 v3 = *reinterpret_cast<const float2*>(hp + (size_t)s3 * F1);
            a0 += w0 * v0.x; a1 += w0 * v0.y;
            a0 += w1 * v1.x; a1 += w1 * v1.y;
            a0 += w2 * v2.x; a1 += w2 * v2.y;
            a0 += w3 * v3.x; a1 += w3 * v3.y;
        }
        for (; j < cn; j++) {
            int s = s_src[j];
            float w = wf[j * 4 + wid];
            float2 hv = *reinterpret_cast<const float2*>(hp + (size_t)s * F1);
            a0 += w * hv.x;
            a1 += w * hv.y;
        }
        __syncthreads();
    }
#pragma unroll
    for (int off = 16; off >= 1; off >>= 1) {
        dpart.x += __shfl_xor_sync(0xffffffffu, dpart.x, off);
        dpart.y += __shfl_xor_sync(0xffffffffu, dpart.y, off);
        dpart.z += __shfl_xor_sync(0xffffffffu, dpart.z, off);
        dpart.w += __shfl_xor_sync(0xffffffffu, dpart.w, off);
    }
    if (lane == 0) s_red[wid] = dpart;
    __syncthreads();
    float4 dt = s_red[0];
    dt.x += s_red[1].x + s_red[2].x + s_red[3].x;
    dt.y += s_red[1].y + s_red[2].y + s_red[3].y;
    dt.z += s_red[1].z + s_red[2].z + s_red[3].z;
    dt.w += s_red[1].w + s_red[2].w + s_red[3].w;
    float den = ((const float*)&dt)[wid] + 1e-16f;
    float inv = 1.f / den;
    int c = tid * 2;
    float o0 = a0 * inv + bias[c];
    float o1 = a1 * inv + bias[c + 1];
    o0 = o0 > 0.f ? roundtf(o0) : 0.f;
    o1 = o1 > 0.f ? roundtf(o1) : 0.f;
    *reinterpret_cast<float2*>(out + (size_t)n * F1 + c) = make_float2(o0, o1);
}

__global__ __launch_bounds__(128) void gat_agg2(
    const float* __restrict__ h, const float* __restrict__ es, const float* __restrict__ ed,
    const float* __restrict__ bias, const float* __restrict__ gamma,
    const float* __restrict__ beta, float* __restrict__ out) {
    int n = blockIdx.x;
    int tid = threadIdx.x;
    int lane = tid & 31, wid = tid >> 5;
    int r0 = g_rowptr[n], r1 = g_rowptr[n + 1];
    int deg = r1 - r0;
    float4 edv = *reinterpret_cast<const float4*>(ed + n * 4);

    __shared__ float4 s_red[4];
    __shared__ int    s_src[CHUNK];
    __shared__ float4 s_w[CHUNK];
    __shared__ float  s_y[F2];
    __shared__ float  s_ln[4];

    const float* hp = h + tid * 4;

    float a0 = 0.f, a1 = 0.f, a2 = 0.f, a3 = 0.f;
    float4 dpart = make_float4(0.f, 0.f, 0.f, 0.f);
    for (int base = 0; base < deg; base += CHUNK) {
        int cn = deg - base; if (cn > CHUNK) cn = CHUNK;
        if (tid < cn) {
            int s = g_srcs[r0 + base + tid];
            float4 w = expleaky4(*reinterpret_cast<const float4*>(es + s * 4), edv);
            s_src[tid] = s;
            s_w[tid] = w;
            dpart.x += w.x; dpart.y += w.y; dpart.z += w.z; dpart.w += w.w;
        }
        __syncthreads();
        const float* wf = reinterpret_cast<const float*>(s_w);
        int j = 0;
        for (; j + 4 <= cn; j += 4) {
            int s0 = s_src[j + 0], s1 = s_src[j + 1];
            int s2 = s_src[j + 2], s3 = s_src[j + 3];
            float w0 = wf[(j + 0) * 4 + wid];
            float w1 = wf[(j + 1) * 4 + wid];
            float w2 = wf[(j + 2) * 4 + wid];
            float w3 = wf[(j + 3) * 4 + wid];
            float4 v0 = *reinterpret_cast<const float4*>(hp + (size_t)s0 * F2);
            float4 v1 = *reinterpret_cast<const float4*>(hp + (size_t)s1 * F2);
            float4 v2 = *reinterpret_cast<const float4*>(hp + (size_t)s2 * F2);
            float4 v3 = *reinterpret_cast<const float4*>(hp + (size_t)s3 * F2);
            a0 += w0 * v0.x; a1 += w0 * v0.y; a2 += w0 * v0.z; a3 += w0 * v0.w;
            a0 += w1 * v1.x; a1 += w1 * v1.y; a2 += w1 * v1.z; a3 += w1 * v1.w;
            a0 += w2 * v2.x; a1 += w2 * v2.y; a2 += w2 * v2.z; a3 += w2 * v2.w;
            a0 += w3 * v3.x; a1 += w3 * v3.y; a2 += w3 * v3.z; a3 += w3 * v3.w;
        }
        for (; j < cn; j++) {
            int s = s_src[j];
            float w = wf[j * 4 + wid];
            float4 hv = *reinterpret_cast<const float4*>(hp + (size_t)s * F2);
            a0 += w * hv.x;
            a1 += w * hv.y;
            a2 += w * hv.z;
            a3 += w * hv.w;
        }
        __syncthreads();
    }
#pragma unroll
    for (int off = 16; off >= 1; off >>= 1) {
        dpart.x += __shfl_xor_sync(0xffffffffu, dpart.x, off);
        dpart.y += __shfl_xor_sync(0xffffffffu, dpart.y, off);
        dpart.z += __shfl_xor_sync(0xffffffffu, dpart.z, off);
        dpart.w += __shfl_xor_sync(0xffffffffu, dpart.w, off);
    }
    if (lane == 0) s_red[wid] = dpart;
    __syncthreads();
    float4 dt = s_red[0];
    dt.x += s_red[1].x + s_red[2].x + s_red[3].x;
    dt.y += s_red[1].y + s_red[2].y + s_red[3].y;
    dt.z += s_red[1].z + s_red[2].z + s_red[3].z;
    dt.w += s_red[1].w + s_red[2].w + s_red[3].w;
    float inv = 1.f / (((const float*)&dt)[wid] + 1e-16f);
    int l = tid * 4;
    s_y[l + 0] = a0 * inv;
    s_y[l + 1] = a1 * inv;
    s_y[l + 2] = a2 * inv;
    s_y[l + 3] = a3 * inv;
    __syncthreads();

    int c = tid;
    float y = 0.25f * (s_y[c] + s_y[128 + c] + s_y[256 + c] + s_y[384 + c]) + bias[c];
    float t = y;
#pragma unroll
    for (int off = 16; off >= 1; off >>= 1) t += __shfl_xor_sync(0xffffffffu, t, off);
    if (lane == 0) s_ln[wid] = t;
    __syncthreads();
    float mu = (s_ln[0] + s_ln[1] + s_ln[2] + s_ln[3]) * (1.f / 128.f);
    float dv = y - mu;
    t = dv * dv;
#pragma unroll
    for (int off = 16; off >= 1; off >>= 1) t += __shfl_xor_sync(0xffffffffu, t, off);
    __syncthreads();
    if (lane == 0) s_ln[wid] = t;
    __syncthreads();
    float var = (s_ln[0] + s_ln[1] + s_ln[2] + s_ln[3]) * (1.f / 128.f);
    out[(size_t)n * 128 + c] = dv * rsqrtf(var + 1e-5f) * gamma[c] + beta[c];
}

// ---------------- launch ----------------
extern "C" void kernel_launch(void* const* d_in, const int* in_sizes, int n_in,
                              void* d_out, int out_size) {
    const float* x     = (const float*)d_in[0];
    const void*  ei    = d_in[1];
    const float* W1    = (const float*)d_in[2];
    const float* as1   = (const float*)d_in[3];
    const float* ad1   = (const float*)d_in[4];
    const float* b1    = (const float*)d_in[5];
    const float* W2    = (const float*)d_in[6];
    const float* as2   = (const float*)d_in[7];
    const float* ad2   = (const float*)d_in[8];
    const float* b2    = (const float*)d_in[9];
    const float* gamma = (const float*)d_in[10];
    const float* beta  = (const float*)d_in[11];
    float*       out   = (float*)d_out;

    float *p_h1, *p_hr, *p_h2, *p_xr, *p_w1r, *p_w2r, *p_es, *p_ed;
    cudaGetSymbolAddress((void**)&p_h1,  g_h1);
    cudaGetSymbolAddress((void**)&p_hr,  g_hr);
    cudaGetSymbolAddress((void**)&p_h2,  g_h2);
    cudaGetSymbolAddress((void**)&p_xr,  g_xr);
    cudaGetSymbolAddress((void**)&p_w1r, g_w1r);
    cudaGetSymbolAddress((void**)&p_w2r, g_w2r);
    cudaGetSymbolAddress((void**)&p_es,  g_es);
    cudaGetSymbolAddress((void**)&p_ed,  g_ed);

    cudaFuncSetAttribute(gemm_db<64>,  cudaFuncAttributeMaxDynamicSharedMemorySize, GEMM_SMEM);
    cudaFuncSetAttribute(gemm_db<128>, cudaFuncAttributeMaxDynamicSharedMemorySize, GEMM_SMEM);

    const int TB = 256;
    int rows128 = (NN + 127) / 128;             // 391
    int edgeBlocks = (ETOT + TB - 1) / TB;      // 3321

    // ---- CSR build + tf32 pre-rounding ----
    detect_idx_kernel<<<1, 32>>>((const int*)ei);
    zero_deg<<<(NN + TB - 1) / TB, TB>>>();
    hist_kernel<<<edgeBlocks, TB>>>(ei);
    scan_tiles<<<NT, 1024>>>();
    scan_parts<<<1, 64>>>();
    add_offsets<<<NT, 1024>>>();
    scatter_kernel<<<edgeBlocks, TB>>>(ei);
    round_copy<<<1024, TB>>>(x,  p_xr,  (size_t)NN * 128 / 4);
    round_copy<<<32,   TB>>>(W1, p_w1r, (size_t)128 * F1 / 4);
    round_copy<<<128,  TB>>>(W2, p_w2r, (size_t)F1 * F2 / 4);

    // ---- layer 1 (scores fused into GEMM epilogue) ----
    gemm_db<64><<<dim3(F1 / 128, rows128), 256, GEMM_SMEM>>>(
        p_xr, p_w1r, p_h1, NN, 128, F1, as1, ad1, p_es, p_ed);
    gat_agg1<<<NN, 128>>>(p_h1, p_es, p_ed, b1, p_hr);

    // ---- layer 2 (scores fused into GEMM epilogue; hr pre-rounded by agg1) ----
    gemm_db<128><<<dim3(F2 / 128, rows128), 256, GEMM_SMEM>>>(
        p_hr, p_w2r, p_h2, NN, 256, F2, as2, ad2, p_es, p_ed);
    gat_agg2<<<NN, 128>>>(p_h2, p_es, p_ed, b2, gamma, beta, out);
}

// round 16
// speedup vs baseline: 1.2329x; 1.2329x over previous
#include <cuda_runtime.h>
#include <cuda_fp16.h>
#include <math.h>

#define NN   50000
#define E0   800000
#define ETOT 850000
#define F1   256          // heads*HID  (layer-1 concat width)
#define F2   512          // heads*OUT  (layer-2 pre-mean width)
#define NT   49           // scan tiles of 1024

// ---------------- scratch (device globals; no allocations) ----------------
__device__ __half g_h1[(size_t)NN * F1];   // layer1 pre-attn features (fp16; only agg1 reads)
__device__ float  g_hr[(size_t)NN * F1];   // layer1 post-attn relu output (GEMM2 input, fp32)
__device__ __half g_h2[(size_t)NN * F2];   // layer2 pre-attn features (fp16; only agg2 reads)
__device__ float  g_es[NN * 4];            // e_src per node/head
__device__ float  g_ed[NN * 4];            // e_dst per node/head
__device__ int    g_deg[NN];
__device__ int    g_rowptr[NN + 1];
__device__ int    g_pos[NN];
__device__ int    g_srcs[ETOT];
__device__ int    g_part[64];
__device__ int    g_partoff[64];
__device__ int    g_is64;

// ---------------- dtype helpers ----------------
__device__ __forceinline__ void edge_nodes(const void* __restrict__ ei, int e,
                                           int& src, int& dst) {
    if (e >= E0) { src = dst = e - E0; return; }
    if (g_is64) {
        const long long* p = (const long long*)ei;
        src = (int)p[e];
        dst = (int)p[E0 + e];
    } else {
        const int* p = (const int*)ei;
        src = p[e];
        dst = p[E0 + e];
    }
}

__global__ void detect_idx_kernel(const int* __restrict__ ei32) {
    if (threadIdx.x == 0) {
        int all0 = 1;
        for (int i = 1; i < 256; i += 2) all0 &= (ei32[i] == 0);
        g_is64 = all0;
    }
}

// ---------------- CSR build ----------------
__global__ void zero_deg() {
    int i = blockIdx.x * blockDim.x + threadIdx.x;
    if (i < NN) g_deg[i] = 0;
}

__global__ void hist_kernel(const void* __restrict__ ei) {
    int e = blockIdx.x * blockDim.x + threadIdx.x;
    if (e >= ETOT) return;
    int src, dst;
    edge_nodes(ei, e, src, dst);
    atomicAdd(&g_deg[dst], 1);
}

__global__ void scan_tiles() {
    __shared__ int warpsum[32];
    int tid = threadIdx.x;
    int i = blockIdx.x * 1024 + tid;
    int lane = tid & 31, wid = tid >> 5;
    int v = (i < NN) ? g_deg[i] : 0;
    int s = v;
#pragma unroll
    for (int off = 1; off < 32; off <<= 1) {
        int t = __shfl_up_sync(0xffffffffu, s, off);
        if (lane >= off) s += t;
    }
    if (lane == 31) warpsum[wid] = s;
    __syncthreads();
    if (wid == 0) {
        int ws = warpsum[lane];
#pragma unroll
        for (int off = 1; off < 32; off <<= 1) {
            int t = __shfl_up_sync(0xffffffffu, ws, off);
            if (lane >= off) ws += t;
        }
        warpsum[lane] = ws;
    }
    __syncthreads();
    int excl = s - v + (wid > 0 ? warpsum[wid - 1] : 0);
    if (i < NN) g_rowptr[i] = excl;
    if (tid == 0) g_part[blockIdx.x] = warpsum[31];
}

__global__ void scan_parts() {
    __shared__ int sp[64];
    int tid = threadIdx.x;
    int v = (tid < NT) ? g_part[tid] : 0;
    sp[tid] = v;
    __syncthreads();
#pragma unroll
    for (int off = 1; off < 64; off <<= 1) {
        int t = sp[tid];
        int add = (tid >= off) ? sp[tid - off] : 0;
        __syncthreads();
        sp[tid] = t + add;
        __syncthreads();
    }
    g_partoff[tid] = sp[tid] - v;
}

__global__ void add_offsets() {
    int i = blockIdx.x * 1024 + threadIdx.x;
    if (i < NN) {
        int r = g_rowptr[i] + g_partoff[blockIdx.x];
        g_rowptr[i] = r;
        g_pos[i]    = r;
    }
    if (i == 0) g_rowptr[NN] = ETOT;
}

__global__ void scatter_kernel(const void* __restrict__ ei) {
    int e = blockIdx.x * blockDim.x + threadIdx.x;
    if (e >= ETOT) return;
    int src, dst;
    edge_nodes(ei, e, src, dst);
    int p = atomicAdd(&g_pos[dst], 1);
    g_srcs[p] = src;
}

// ---------------- tf32 GEMM, 128x128 tile, cp.async 2-stage, fused attn scores ----
// Output C is fp16 (half2 pairs); scores computed fp32 from accumulators.
__device__ __forceinline__ unsigned f2tf32(float f) {
    unsigned r;
    asm("cvt.rna.tf32.f32 %0, %1;" : "=r"(r) : "f"(f));
    return r;
}
__device__ __forceinline__ void mma_tf32(float* d, const unsigned* a, const unsigned* b) {
    asm volatile(
        "mma.sync.aligned.m16n8k8.row.col.f32.tf32.tf32.f32 "
        "{%0,%1,%2,%3}, {%4,%5,%6,%7}, {%8,%9}, {%0,%1,%2,%3};"
        : "+f"(d[0]), "+f"(d[1]), "+f"(d[2]), "+f"(d[3])
        : "r"(a[0]), "r"(a[1]), "r"(a[2]), "r"(a[3]), "r"(b[0]), "r"(b[1]));
}
__device__ __forceinline__ void cp_async16(unsigned saddr, const void* gaddr, int srcb) {
    asm volatile("cp.async.ca.shared.global [%0], [%1], 16, %2;"
                 :: "r"(saddr), "l"(gaddr), "r"(srcb));
}

#define AS_STRIDE 36
#define BS_STRIDE 136
#define AS_ELEMS  (128 * AS_STRIDE)
#define BS_ELEMS  (32 * BS_STRIDE)
#define GEMM_SMEM ((2 * AS_ELEMS + 2 * BS_ELEMS) * 4)   // 71680 B

// CH = per-head channel count for fused attention scores.
template <int CH>
__global__ __launch_bounds__(256) void gemm_db(const float* __restrict__ A,
                                               const float* __restrict__ B,
                                               __half* __restrict__ C,
                                               int n, int K, int J,
                                               const float* __restrict__ a_src,
                                               const float* __restrict__ a_dst,
                                               float* __restrict__ es,
                                               float* __restrict__ ed) {
    extern __shared__ float sm[];
    float* As = sm;
    float* Bs = sm + 2 * AS_ELEMS;
    int tid  = threadIdx.x;
    int warp = tid >> 5, lane = tid & 31;
    int wm = (warp & 3) * 32;
    int wn = (warp >> 2) * 64;
    int row0 = blockIdx.y * 128;
    int col0 = blockIdx.x * 128;
    int lr = lane >> 2, lc = lane & 3;

    unsigned as_base = (unsigned)__cvta_generic_to_shared(As);
    unsigned bs_base = (unsigned)__cvta_generic_to_shared(Bs);

    float acc[2][8][4];
#pragma unroll
    for (int i = 0; i < 2; i++)
#pragma unroll
        for (int j = 0; j < 8; j++)
#pragma unroll
            for (int q = 0; q < 4; q++) acc[i][j][q] = 0.f;

    auto issue = [&](int st, int k0) {
#pragma unroll
        for (int q = 0; q < 4; q++) {
            int c = tid + q * 256;
            int ar = c >> 3, kc = (c & 7) * 4;
            int grow = row0 + ar;
            unsigned dst = as_base + (st * AS_ELEMS + ar * AS_STRIDE + kc) * 4;
            const float* src = A + (size_t)grow * K + k0 + kc;
            cp_async16(dst, src, (grow < n) ? 16 : 0);
        }
#pragma unroll
        for (int q = 0; q < 4; q++) {
            int c = tid + q * 256;
            int br = c >> 5, bc = (c & 31) * 4;
            unsigned dst = bs_base + (st * BS_ELEMS + br * BS_STRIDE + bc) * 4;
            const float* src = B + (size_t)(k0 + br) * J + col0 + bc;
            cp_async16(dst, src, 16);
        }
        asm volatile("cp.async.commit_group;");
    };

    issue(0, 0);
    int st = 0;
    for (int k0 = 0; k0 < K; k0 += 32, st ^= 1) {
        if (k0 + 32 < K) {
            issue(st ^ 1, k0 + 32);
            asm volatile("cp.async.wait_group 1;");
        } else {
            asm volatile("cp.async.wait_group 0;");
        }
        __syncthreads();
        const float* as = As + st * AS_ELEMS;
        const float* bs = Bs + st * BS_ELEMS;
#pragma unroll
        for (int kk = 0; kk < 32; kk += 8) {
            unsigned a[2][4], b[8][2];
#pragma unroll
            for (int mf = 0; mf < 2; mf++) {
                int r = wm + mf * 16 + lr;
                a[mf][0] = f2tf32(as[r * AS_STRIDE + kk + lc]);
                a[mf][1] = f2tf32(as[(r + 8) * AS_STRIDE + kk + lc]);
                a[mf][2] = f2tf32(as[r * AS_STRIDE + kk + lc + 4]);
                a[mf][3] = f2tf32(as[(r + 8) * AS_STRIDE + kk + lc + 4]);
            }
#pragma unroll
            for (int nf = 0; nf < 8; nf++) {
                int c = wn + nf * 8 + lr;
                b[nf][0] = f2tf32(bs[(kk + lc) * BS_STRIDE + c]);
                b[nf][1] = f2tf32(bs[(kk + lc + 4) * BS_STRIDE + c]);
            }
#pragma unroll
            for (int mf = 0; mf < 2; mf++)
#pragma unroll
                for (int nf = 0; nf < 8; nf++)
                    mma_tf32(acc[mf][nf], a[mf], b[nf]);
        }
        __syncthreads();
    }

    // ---- store C as fp16 (c even -> 4B-aligned half2) ----
#pragma unroll
    for (int mf = 0; mf < 2; mf++) {
#pragma unroll
        for (int nf = 0; nf < 8; nf++) {
            int r = row0 + wm + mf * 16 + lr;
            int c = col0 + wn + nf * 8 + 2 * lc;
            if (r < n)
                *reinterpret_cast<__half2*>(C + (size_t)r * J + c) =
                    __floats2half2_rn(acc[mf][nf][0], acc[mf][nf][1]);
            if (r + 8 < n)
                *reinterpret_cast<__half2*>(C + (size_t)(r + 8) * J + c) =
                    __floats2half2_rn(acc[mf][nf][2], acc[mf][nf][3]);
        }
    }

    // ---- fused attention scores from accumulators (fp32, same as R14) ----
    {
        int head0 = (col0 + wn) / CH;
        float psrc[4] = {0.f, 0.f, 0.f, 0.f};
        float pdst[4] = {0.f, 0.f, 0.f, 0.f};
#pragma unroll
        for (int nf = 0; nf < 8; nf++) {
            int cin = (col0 + wn + nf * 8 + 2 * lc) % CH;
            float a0s = a_src[head0 * CH + cin], a1s = a_src[head0 * CH + cin + 1];
            float a0d = a_dst[head0 * CH + cin], a1d = a_dst[head0 * CH + cin + 1];
#pragma unroll
            for (int mf = 0; mf < 2; mf++) {
                psrc[mf * 2 + 0] += acc[mf][nf][0] * a0s + acc[mf][nf][1] * a1s;
                pdst[mf * 2 + 0] += acc[mf][nf][0] * a0d + acc[mf][nf][1] * a1d;
                psrc[mf * 2 + 1] += acc[mf][nf][2] * a0s + acc[mf][nf][3] * a1s;
                pdst[mf * 2 + 1] += acc[mf][nf][2] * a0d + acc[mf][nf][3] * a1d;
            }
        }
#pragma unroll
        for (int off = 1; off <= 2; off <<= 1) {
#pragma unroll
            for (int i = 0; i < 4; i++) {
                psrc[i] += __shfl_down_sync(0xffffffffu, psrc[i], off);
                pdst[i] += __shfl_down_sync(0xffffffffu, pdst[i], off);
            }
        }
        float* part = sm;
        if (lc == 0) {
            int nw = warp >> 2;
#pragma unroll
            for (int i = 0; i < 4; i++) {
                int row = wm + (i >> 1) * 16 + lr + (i & 1) * 8;
                part[(row * 2 + nw) * 2 + 0] = psrc[i];
                part[(row * 2 + nw) * 2 + 1] = pdst[i];
            }
        }
        __syncthreads();
        if (tid < 128) {
            int grow = row0 + tid;
            if (grow < n) {
                if (CH == 64) {
                    int h0 = col0 / 64;
                    es[grow * 4 + h0]     = part[(tid * 2 + 0) * 2 + 0];
                    ed[grow * 4 + h0]     = part[(tid * 2 + 0) * 2 + 1];
                    es[grow * 4 + h0 + 1] = part[(tid * 2 + 1) * 2 + 0];
                    ed[grow * 4 + h0 + 1] = part[(tid * 2 + 1) * 2 + 1];
                } else {
                    int h = col0 / 128;
                    es[grow * 4 + h] = part[(tid * 2 + 0) * 2 + 0] + part[(tid * 2 + 1) * 2 + 0];
                    ed[grow * 4 + h] = part[(tid * 2 + 0) * 2 + 1] + part[(tid * 2 + 1) * 2 + 1];
                }
            }
        }
    }
}

// ---------------- fused per-node GAT aggregation (fp16 gathers, fp32 accum) ---------
__device__ __forceinline__ float4 expleaky4(float4 a, float4 b) {
    float4 v;
    v.x = a.x + b.x; v.x = v.x > 0.f ? v.x : 0.2f * v.x; v.x = __expf(v.x);
    v.y = a.y + b.y; v.y = v.y > 0.f ? v.y : 0.2f * v.y; v.y = __expf(v.y);
    v.z = a.z + b.z; v.z = v.z > 0.f ? v.z : 0.2f * v.z; v.z = __expf(v.z);
    v.w = a.w + b.w; v.w = v.w > 0.f ? v.w : 0.2f * v.w; v.w = __expf(v.w);
    return v;
}

#define CHUNK 64

__global__ __launch_bounds__(128) void gat_agg1(
    const __half* __restrict__ h, const float* __restrict__ es, const float* __restrict__ ed,
    const float* __restrict__ bias, float* __restrict__ out) {
    int n = blockIdx.x;
    int tid = threadIdx.x;
    int lane = tid & 31, wid = tid >> 5;
    int r0 = g_rowptr[n], r1 = g_rowptr[n + 1];
    int deg = r1 - r0;
    float4 edv = *reinterpret_cast<const float4*>(ed + n * 4);

    __shared__ float4 s_red[4];
    __shared__ int    s_src[CHUNK];
    __shared__ float4 s_w[CHUNK];

    const __half2* hp = reinterpret_cast<const __half2*>(h) + tid;  // + s*F1/2 per row

    float a0 = 0.f, a1 = 0.f;
    float4 dpart = make_float4(0.f, 0.f, 0.f, 0.f);
    for (int base = 0; base < deg; base += CHUNK) {
        int cn = deg - base; if (cn > CHUNK) cn = CHUNK;
        if (tid < cn) {
            int s = g_srcs[r0 + base + tid];
            float4 w = expleaky4(*reinterpret_cast<const float4*>(es + s * 4), edv);
            s_src[tid] = s;
            s_w[tid] = w;
            dpart.x += w.x; dpart.y += w.y; dpart.z += w.z; dpart.w += w.w;
        }
        __syncthreads();
        const float* wf = reinterpret_cast<const float*>(s_w);
        int j = 0;
        for (; j + 4 <= cn; j += 4) {
            int s0 = s_src[j + 0], s1 = s_src[j + 1];
            int s2 = s_src[j + 2], s3 = s_src[j + 3];
            float w0 = wf[(j + 0) * 4 + wid];
            float w1 = wf[(j + 1) * 4 + wid];
            float w2 = wf[(j + 2) * 4 + wid];
            float w3 = wf[(j + 3) * 4 + wid];
            float2 v0 = __half22float2(hp[(size_t)s0 * (F1 / 2)]);
            float2 v1 = __half22float2(hp[(size_t)s1 * (F1 / 2)]);
            float2 v2 = __half22float2(hp[(size_t)s2 * (F1 / 2)]);
            float2 v3 = __half22float2(hp[(size_t)s3 * (F1 / 2)]);
            a0 += w0 * v0.x; a1 += w0 * v0.y;
            a0 += w1 * v1.x; a1 += w1 * v1.y;
            a0 += w2 * v2.x; a1 += w2 * v2.y;
            a0 += w3 * v3.x; a1 += w3 * v3.y;
        }
        for (; j < cn; j++) {
            int s = s_src[j];
            float w = wf[j * 4 + wid];
            float2 hv = __half22float2(hp[(size_t)s * (F1 / 2)]);
            a0 += w * hv.x;
            a1 += w * hv.y;
        }
        __syncthreads();
    }
#pragma unroll
    for (int off = 16; off >= 1; off >>= 1) {
        dpart.x += __shfl_xor_sync(0xffffffffu, dpart.x, off);
        dpart.y += __shfl_xor_sync(0xffffffffu, dpart.y, off);
        dpart.z += __shfl_xor_sync(0xffffffffu, dpart.z, off);
        dpart.w += __shfl_xor_sync(0xffffffffu, dpart.w, off);
    }
    if (lane == 0) s_red[wid] = dpart;
    __syncthreads();
    float4 dt = s_red[0];
    dt.x += s_red[1].x + s_red[2].x + s_red[3].x;
    dt.y += s_red[1].y + s_red[2].y + s_red[3].y;
    dt.z += s_red[1].z + s_red[2].z + s_red[3].z;
    dt.w += s_red[1].w + s_red[2].w + s_red[3].w;
    float den = ((const float*)&dt)[wid] + 1e-16f;
    float inv = 1.f / den;
    int c = tid * 2;
    float o0 = a0 * inv + bias[c];
    float o1 = a1 * inv + bias[c + 1];
    o0 = o0 > 0.f ? o0 : 0.f;
    o1 = o1 > 0.f ? o1 : 0.f;
    *reinterpret_cast<float2*>(out + (size_t)n * F1 + c) = make_float2(o0, o1);
}

__global__ __launch_bounds__(128) void gat_agg2(
    const __half* __restrict__ h, const float* __restrict__ es, const float* __restrict__ ed,
    const float* __restrict__ bias, const float* __restrict__ gamma,
    const float* __restrict__ beta, float* __restrict__ out) {
    int n = blockIdx.x;
    int tid = threadIdx.x;
    int lane = tid & 31, wid = tid >> 5;
    int r0 = g_rowptr[n], r1 = g_rowptr[n + 1];
    int deg = r1 - r0;
    float4 edv = *reinterpret_cast<const float4*>(ed + n * 4);

    __shared__ float4 s_red[4];
    __shared__ int    s_src[CHUNK];
    __shared__ float4 s_w[CHUNK];
    __shared__ float  s_y[F2];
    __shared__ float  s_ln[4];

    const uint2* hp = reinterpret_cast<const uint2*>(h) + tid;  // + s*F2/4 per row

    float a0 = 0.f, a1 = 0.f, a2 = 0.f, a3 = 0.f;
    float4 dpart = make_float4(0.f, 0.f, 0.f, 0.f);
    for (int base = 0; base < deg; base += CHUNK) {
        int cn = deg - base; if (cn > CHUNK) cn = CHUNK;
        if (tid < cn) {
            int s = g_srcs[r0 + base + tid];
            float4 w = expleaky4(*reinterpret_cast<const float4*>(es + s * 4), edv);
            s_src[tid] = s;
            s_w[tid] = w;
            dpart.x += w.x; dpart.y += w.y; dpart.z += w.z; dpart.w += w.w;
        }
        __syncthreads();
        const float* wf = reinterpret_cast<const float*>(s_w);
        int j = 0;
        for (; j + 4 <= cn; j += 4) {
            int s0 = s_src[j + 0], s1 = s_src[j + 1];
            int s2 = s_src[j + 2], s3 = s_src[j + 3];
            float w0 = wf[(j + 0) * 4 + wid];
            float w1 = wf[(j + 1) * 4 + wid];
            float w2 = wf[(j + 2) * 4 + wid];
            float w3 = wf[(j + 3) * 4 + wid];
            uint2 r0v = hp[(size_t)s0 * (F2 / 4)];
            uint2 r1v = hp[(size_t)s1 * (F2 / 4)];
            uint2 r2v = hp[(size_t)s2 * (F2 / 4)];
            uint2 r3v = hp[(size_t)s3 * (F2 / 4)];
            float2 p0 = __half22float2(*reinterpret_cast<__half2*>(&r0v.x));
            float2 q0 = __half22float2(*reinterpret_cast<__half2*>(&r0v.y));
            float2 p1 = __half22float2(*reinterpret_cast<__half2*>(&r1v.x));
            float2 q1 = __half22float2(*reinterpret_cast<__half2*>(&r1v.y));
            float2 p2 = __half22float2(*reinterpret_cast<__half2*>(&r2v.x));
            float2 q2 = __half22float2(*reinterpret_cast<__half2*>(&r2v.y));
            float2 p3 = __half22float2(*reinterpret_cast<__half2*>(&r3v.x));
            float2 q3 = __half22float2(*reinterpret_cast<__half2*>(&r3v.y));
            a0 += w0 * p0.x; a1 += w0 * p0.y; a2 += w0 * q0.x; a3 += w0 * q0.y;
            a0 += w1 * p1.x; a1 += w1 * p1.y; a2 += w1 * q1.x; a3 += w1 * q1.y;
            a0 += w2 * p2.x; a1 += w2 * p2.y; a2 += w2 * q2.x; a3 += w2 * q2.y;
            a0 += w3 * p3.x; a1 += w3 * p3.y; a2 += w3 * q3.x; a3 += w3 * q3.y;
        }
        for (; j < cn; j++) {
            int s = s_src[j];
            float w = wf[j * 4 + wid];
            uint2 rv = hp[(size_t)s * (F2 / 4)];
            float2 p = __half22float2(*reinterpret_cast<__half2*>(&rv.x));
            float2 q = __half22float2(*reinterpret_cast<__half2*>(&rv.y));
            a0 += w * p.x; a1 += w * p.y; a2 += w * q.x; a3 += w * q.y;
        }
        __syncthreads();
    }
#pragma unroll
    for (int off = 16; off >= 1; off >>= 1) {
        dpart.x += __shfl_xor_sync(0xffffffffu, dpart.x, off);
        dpart.y += __shfl_xor_sync(0xffffffffu, dpart.y, off);
        dpart.z += __shfl_xor_sync(0xffffffffu, dpart.z, off);
        dpart.w += __shfl_xor_sync(0xffffffffu, dpart.w, off);
    }
    if (lane == 0) s_red[wid] = dpart;
    __syncthreads();
    float4 dt = s_red[0];
    dt.x += s_red[1].x + s_red[2].x + s_red[3].x;
    dt.y += s_red[1].y + s_red[2].y + s_red[3].y;
    dt.z += s_red[1].z + s_red[2].z + s_red[3].z;
    dt.w += s_red[1].w + s_red[2].w + s_red[3].w;
    float inv = 1.f / (((const float*)&dt)[wid] + 1e-16f);
    int l = tid * 4;
    s_y[l + 0] = a0 * inv;
    s_y[l + 1] = a1 * inv;
    s_y[l + 2] = a2 * inv;
    s_y[l + 3] = a3 * inv;
    __syncthreads();

    int c = tid;
    float y = 0.25f * (s_y[c] + s_y[128 + c] + s_y[256 + c] + s_y[384 + c]) + bias[c];
    float t = y;
#pragma unroll
    for (int off = 16; off >= 1; off >>= 1) t += __shfl_xor_sync(0xffffffffu, t, off);
    if (lane == 0) s_ln[wid] = t;
    __syncthreads();
    float mu = (s_ln[0] + s_ln[1] + s_ln[2] + s_ln[3]) * (1.f / 128.f);
    float dv = y - mu;
    t = dv * dv;
#pragma unroll
    for (int off = 16; off >= 1; off >>= 1) t += __shfl_xor_sync(0xffffffffu, t, off);
    __syncthreads();
    if (lane == 0) s_ln[wid] = t;
    __syncthreads();
    float var = (s_ln[0] + s_ln[1] + s_ln[2] + s_ln[3]) * (1.f / 128.f);
    out[(size_t)n * 128 + c] = dv * rsqrtf(var + 1e-5f) * gamma[c] + beta[c];
}

// ---------------- launch ----------------
extern "C" void kernel_launch(void* const* d_in, const int* in_sizes, int n_in,
                              void* d_out, int out_size) {
    const float* x     = (const float*)d_in[0];
    const void*  ei    = d_in[1];
    const float* W1    = (const float*)d_in[2];
    const float* as1   = (const float*)d_in[3];
    const float* ad1   = (const float*)d_in[4];
    const float* b1    = (const float*)d_in[5];
    const float* W2    = (const float*)d_in[6];
    const float* as2   = (const float*)d_in[7];
    const float* ad2   = (const float*)d_in[8];
    const float* b2    = (const float*)d_in[9];
    const float* gamma = (const float*)d_in[10];
    const float* beta  = (const float*)d_in[11];
    float*       out   = (float*)d_out;

    __half *p_h1, *p_h2;
    float *p_hr, *p_es, *p_ed;
    cudaGetSymbolAddress((void**)&p_h1, g_h1);
    cudaGetSymbolAddress((void**)&p_hr, g_hr);
    cudaGetSymbolAddress((void**)&p_h2, g_h2);
    cudaGetSymbolAddress((void**)&p_es, g_es);
    cudaGetSymbolAddress((void**)&p_ed, g_ed);

    cudaFuncSetAttribute(gemm_db<64>,  cudaFuncAttributeMaxDynamicSharedMemorySize, GEMM_SMEM);
    cudaFuncSetAttribute(gemm_db<128>, cudaFuncAttributeMaxDynamicSharedMemorySize, GEMM_SMEM);

    const int TB = 256;
    int rows128 = (NN + 127) / 128;             // 391
    int edgeBlocks = (ETOT + TB - 1) / TB;      // 3321

    // ---- CSR build ----
    detect_idx_kernel<<<1, 32>>>((const int*)ei);
    zero_deg<<<(NN + TB - 1) / TB, TB>>>();
    hist_kernel<<<edgeBlocks, TB>>>(ei);
    scan_tiles<<<NT, 1024>>>();
    scan_parts<<<1, 64>>>();
    add_offsets<<<NT, 1024>>>();
    scatter_kernel<<<edgeBlocks, TB>>>(ei);

    // ---- layer 1 (scores fused into GEMM epilogue; h1 stored fp16) ----
    gemm_db<64><<<dim3(F1 / 128, rows128), 256, GEMM_SMEM>>>(
        x, W1, p_h1, NN, 128, F1, as1, ad1, p_es, p_ed);
    gat_agg1<<<NN, 128>>>(p_h1, p_es, p_ed, b1, p_hr);

    // ---- layer 2 (scores fused into GEMM epilogue; h2 stored fp16) ----
    gemm_db<128><<<dim3(F2 / 128, rows128), 256, GEMM_SMEM>>>(
        p_hr, W2, p_h2, NN, 256, F2, as2, ad2, p_es, p_ed);
    gat_agg2<<<NN, 128>>>(p_h2, p_es, p_ed, b2, gamma, beta, out);
}

// round 17
// speedup vs baseline: 1.3466x; 1.0922x over previous
#include <cuda_runtime.h>
#include <cuda_fp16.h>
#include <math.h>

#define NN   50000
#define E0   800000
#define ETOT 850000
#define F1   256          // heads*HID  (layer-1 concat width)
#define F2   512          // heads*OUT  (layer-2 pre-mean width)
#define NT   49           // scan tiles of 1024

// ---------------- scratch (device globals; no allocations) ----------------
__device__ __half g_h1[(size_t)NN * F1];   // layer1 pre-attn features (fp16)
__device__ __half g_hr[(size_t)NN * F1];   // layer1 post-attn relu output (fp16, GEMM2 A)
__device__ __half g_h2[(size_t)NN * F2];   // layer2 pre-attn features (fp16)
__device__ __half g_xh[(size_t)NN * 128];  // fp16 x
__device__ __half g_w1t[F1 * 128];         // W1^T fp16: [j][k]
__device__ __half g_w2t[F2 * F1];          // W2^T fp16: [j][k]
__device__ float  g_es[NN * 4];            // e_src per node/head
__device__ float  g_ed[NN * 4];            // e_dst per node/head
__device__ int    g_deg[NN];
__device__ int    g_rowptr[NN + 1];
__device__ int    g_pos[NN];
__device__ int    g_srcs[ETOT];
__device__ int    g_part[64];
__device__ int    g_partoff[64];
__device__ int    g_is64;

// ---------------- dtype helpers ----------------
__device__ __forceinline__ void edge_nodes(const void* __restrict__ ei, int e,
                                           int& src, int& dst) {
    if (e >= E0) { src = dst = e - E0; return; }
    if (g_is64) {
        const long long* p = (const long long*)ei;
        src = (int)p[e];
        dst = (int)p[E0 + e];
    } else {
        const int* p = (const int*)ei;
        src = p[e];
        dst = p[E0 + e];
    }
}

__global__ void detect_idx_kernel(const int* __restrict__ ei32) {
    if (threadIdx.x == 0) {
        int all0 = 1;
        for (int i = 1; i < 256; i += 2) all0 &= (ei32[i] == 0);
        g_is64 = all0;
    }
}

// fp32 -> fp16 pairwise copy
__global__ void f2h_copy(const float* __restrict__ s, __half* __restrict__ d, int n2) {
    int i  = blockIdx.x * blockDim.x + threadIdx.x;
    int st = gridDim.x * blockDim.x;
    const float2* s2 = reinterpret_cast<const float2*>(s);
    __half2* d2 = reinterpret_cast<__half2*>(d);
    for (int j = i; j < n2; j += st)
        d2[j] = __floats2half2_rn(s2[j].x, s2[j].y);
}

// W[R][C] fp32 -> Wt[C][R] fp16
__global__ void transpose_h(const float* __restrict__ W, __half* __restrict__ Wt,
                            int R, int C) {
    int i = blockIdx.x * blockDim.x + threadIdx.x;
    if (i >= R * C) return;
    int j = i / R;          // out row (0..C-1)
    int k = i - j * R;      // out col (0..R-1)
    Wt[i] = __float2half(W[k * C + j]);
}

// ---------------- CSR build ----------------
__global__ void zero_deg() {
    int i = blockIdx.x * blockDim.x + threadIdx.x;
    if (i < NN) g_deg[i] = 0;
}

__global__ void hist_kernel(const void* __restrict__ ei) {
    int e = blockIdx.x * blockDim.x + threadIdx.x;
    if (e >= ETOT) return;
    int src, dst;
    edge_nodes(ei, e, src, dst);
    atomicAdd(&g_deg[dst], 1);
}

__global__ void scan_tiles() {
    __shared__ int warpsum[32];
    int tid = threadIdx.x;
    int i = blockIdx.x * 1024 + tid;
    int lane = tid & 31, wid = tid >> 5;
    int v = (i < NN) ? g_deg[i] : 0;
    int s = v;
#pragma unroll
    for (int off = 1; off < 32; off <<= 1) {
        int t = __shfl_up_sync(0xffffffffu, s, off);
        if (lane >= off) s += t;
    }
    if (lane == 31) warpsum[wid] = s;
    __syncthreads();
    if (wid == 0) {
        int ws = warpsum[lane];
#pragma unroll
        for (int off = 1; off < 32; off <<= 1) {
            int t = __shfl_up_sync(0xffffffffu, ws, off);
            if (lane >= off) ws += t;
        }
        warpsum[lane] = ws;
    }
    __syncthreads();
    int excl = s - v + (wid > 0 ? warpsum[wid - 1] : 0);
    if (i < NN) g_rowptr[i] = excl;
    if (tid == 0) g_part[blockIdx.x] = warpsum[31];
}

__global__ void scan_parts() {
    __shared__ int sp[64];
    int tid = threadIdx.x;
    int v = (tid < NT) ? g_part[tid] : 0;
    sp[tid] = v;
    __syncthreads();
#pragma unroll
    for (int off = 1; off < 64; off <<= 1) {
        int t = sp[tid];
        int add = (tid >= off) ? sp[tid - off] : 0;
        __syncthreads();
        sp[tid] = t + add;
        __syncthreads();
    }
    g_partoff[tid] = sp[tid] - v;
}

__global__ void add_offsets() {
    int i = blockIdx.x * 1024 + threadIdx.x;
    if (i < NN) {
        int r = g_rowptr[i] + g_partoff[blockIdx.x];
        g_rowptr[i] = r;
        g_pos[i]    = r;
    }
    if (i == 0) g_rowptr[NN] = ETOT;
}

__global__ void scatter_kernel(const void* __restrict__ ei) {
    int e = blockIdx.x * blockDim.x + threadIdx.x;
    if (e >= ETOT) return;
    int src, dst;
    edge_nodes(ei, e, src, dst);
    int p = atomicAdd(&g_pos[dst], 1);
    g_srcs[p] = src;
}

// ---------------- fp16 GEMM m16n8k16, 128x128 tile, cp.async 2-stage ---------------
// A [n][K] fp16 row-major; Bt [J][K] fp16 (i.e. B transposed, n-major).
// C stored fp16; fused fp32 attention scores from accumulators.
__device__ __forceinline__ void mma_f16(float* d, const unsigned* a, const unsigned* b) {
    asm volatile(
        "mma.sync.aligned.m16n8k16.row.col.f32.f16.f16.f32 "
        "{%0,%1,%2,%3}, {%4,%5,%6,%7}, {%8,%9}, {%0,%1,%2,%3};"
        : "+f"(d[0]), "+f"(d[1]), "+f"(d[2]), "+f"(d[3])
        : "r"(a[0]), "r"(a[1]), "r"(a[2]), "r"(a[3]), "r"(b[0]), "r"(b[1]));
}
__device__ __forceinline__ void cp_async16(unsigned saddr, const void* gaddr, int srcb) {
    asm volatile("cp.async.ca.shared.global [%0], [%1], 16, %2;"
                 :: "r"(saddr), "l"(gaddr), "r"(srcb));
}

#define AH_STRIDE 40                     // halves; banks (20*r+lc)%32 all distinct
#define AH_ELEMS  (128 * AH_STRIDE)      // one stage
#define BH_ELEMS  (128 * AH_STRIDE)

// CH = per-head channel count for fused attention scores.
template <int CH>
__global__ __launch_bounds__(256) void gemm_h16(const __half* __restrict__ A,
                                                const __half* __restrict__ Bt,
                                                __half* __restrict__ C,
                                                int n, int K, int J,
                                                const float* __restrict__ a_src,
                                                const float* __restrict__ a_dst,
                                                float* __restrict__ es,
                                                float* __restrict__ ed) {
    __shared__ __half smA[2 * AH_ELEMS];
    __shared__ __half smB[2 * BH_ELEMS];
    int tid  = threadIdx.x;
    int warp = tid >> 5, lane = tid & 31;
    int wm = (warp & 3) * 32;
    int wn = (warp >> 2) * 64;
    int row0 = blockIdx.y * 128;
    int col0 = blockIdx.x * 128;
    int lr = lane >> 2, lc = lane & 3;

    unsigned as_base = (unsigned)__cvta_generic_to_shared(smA);
    unsigned bs_base = (unsigned)__cvta_generic_to_shared(smB);

    float acc[2][8][4];
#pragma unroll
    for (int i = 0; i < 2; i++)
#pragma unroll
        for (int j = 0; j < 8; j++)
#pragma unroll
            for (int q = 0; q < 4; q++) acc[i][j][q] = 0.f;

    // per k0: A tile 128 rows x 32 halves (4 chunks of 8 halves); B same from Bt.
    auto issue = [&](int st, int k0) {
#pragma unroll
        for (int q = 0; q < 2; q++) {
            int c = tid + q * 256;           // 0..511
            int ar = c >> 2, kc = (c & 3) * 8;
            int grow = row0 + ar;
            unsigned dst = as_base + (st * AH_ELEMS + ar * AH_STRIDE + kc) * 2;
            const __half* src = A + (size_t)grow * K + k0 + kc;
            cp_async16(dst, src, (grow < n) ? 16 : 0);
        }
#pragma unroll
        for (int q = 0; q < 2; q++) {
            int c = tid + q * 256;
            int nr = c >> 2, kc = (c & 3) * 8;
            unsigned dst = bs_base + (st * BH_ELEMS + nr * AH_STRIDE + kc) * 2;
            const __half* src = Bt + (size_t)(col0 + nr) * K + k0 + kc;
            cp_async16(dst, src, 16);
        }
        asm volatile("cp.async.commit_group;");
    };

    issue(0, 0);
    int st = 0;
    for (int k0 = 0; k0 < K; k0 += 32, st ^= 1) {
        if (k0 + 32 < K) {
            issue(st ^ 1, k0 + 32);
            asm volatile("cp.async.wait_group 1;");
        } else {
            asm volatile("cp.async.wait_group 0;");
        }
        __syncthreads();
        const __half* as = smA + st * AH_ELEMS;
        const __half* bs = smB + st * BH_ELEMS;
#pragma unroll
        for (int kk = 0; kk < 32; kk += 16) {
            unsigned a[2][4], b[8][2];
#pragma unroll
            for (int mf = 0; mf < 2; mf++) {
                int r = wm + mf * 16 + lr;
                a[mf][0] = *reinterpret_cast<const unsigned*>(as + r * AH_STRIDE + kk + 2 * lc);
                a[mf][1] = *reinterpret_cast<const unsigned*>(as + (r + 8) * AH_STRIDE + kk + 2 * lc);
                a[mf][2] = *reinterpret_cast<const unsigned*>(as + r * AH_STRIDE + kk + 2 * lc + 8);
                a[mf][3] = *reinterpret_cast<const unsigned*>(as + (r + 8) * AH_STRIDE + kk + 2 * lc + 8);
            }
#pragma unroll
            for (int nf = 0; nf < 8; nf++) {
                int c = wn + nf * 8 + lr;
                b[nf][0] = *reinterpret_cast<const unsigned*>(bs + c * AH_STRIDE + kk + 2 * lc);
                b[nf][1] = *reinterpret_cast<const unsigned*>(bs + c * AH_STRIDE + kk + 2 * lc + 8);
            }
#pragma unroll
            for (int mf = 0; mf < 2; mf++)
#pragma unroll
                for (int nf = 0; nf < 8; nf++)
                    mma_f16(acc[mf][nf], a[mf], b[nf]);
        }
        __syncthreads();
    }

    // ---- store C as fp16 (c even -> 4B-aligned half2) ----
#pragma unroll
    for (int mf = 0; mf < 2; mf++) {
#pragma unroll
        for (int nf = 0; nf < 8; nf++) {
            int r = row0 + wm + mf * 16 + lr;
            int c = col0 + wn + nf * 8 + 2 * lc;
            if (r < n)
                *reinterpret_cast<__half2*>(C + (size_t)r * J + c) =
                    __floats2half2_rn(acc[mf][nf][0], acc[mf][nf][1]);
            if (r + 8 < n)
                *reinterpret_cast<__half2*>(C + (size_t)(r + 8) * J + c) =
                    __floats2half2_rn(acc[mf][nf][2], acc[mf][nf][3]);
        }
    }

    // ---- fused attention scores from accumulators (fp32) ----
    {
        int head0 = (col0 + wn) / CH;
        float psrc[4] = {0.f, 0.f, 0.f, 0.f};
        float pdst[4] = {0.f, 0.f, 0.f, 0.f};
#pragma unroll
        for (int nf = 0; nf < 8; nf++) {
            int cin = (col0 + wn + nf * 8 + 2 * lc) % CH;
            float a0s = a_src[head0 * CH + cin], a1s = a_src[head0 * CH + cin + 1];
            float a0d = a_dst[head0 * CH + cin], a1d = a_dst[head0 * CH + cin + 1];
#pragma unroll
            for (int mf = 0; mf < 2; mf++) {
                psrc[mf * 2 + 0] += acc[mf][nf][0] * a0s + acc[mf][nf][1] * a1s;
                pdst[mf * 2 + 0] += acc[mf][nf][0] * a0d + acc[mf][nf][1] * a1d;
                psrc[mf * 2 + 1] += acc[mf][nf][2] * a0s + acc[mf][nf][3] * a1s;
                pdst[mf * 2 + 1] += acc[mf][nf][2] * a0d + acc[mf][nf][3] * a1d;
            }
        }
#pragma unroll
        for (int off = 1; off <= 2; off <<= 1) {
#pragma unroll
            for (int i = 0; i < 4; i++) {
                psrc[i] += __shfl_down_sync(0xffffffffu, psrc[i], off);
                pdst[i] += __shfl_down_sync(0xffffffffu, pdst[i], off);
            }
        }
        float* part = reinterpret_cast<float*>(smA);   // 512 floats scratch
        if (lc == 0) {
            int nw = warp >> 2;
#pragma unroll
            for (int i = 0; i < 4; i++) {
                int row = wm + (i >> 1) * 16 + lr + (i & 1) * 8;
                part[(row * 2 + nw) * 2 + 0] = psrc[i];
                part[(row * 2 + nw) * 2 + 1] = pdst[i];
            }
        }
        __syncthreads();
        if (tid < 128) {
            int grow = row0 + tid;
            if (grow < n) {
                if (CH == 64) {
                    int h0 = col0 / 64;
                    es[grow * 4 + h0]     = part[(tid * 2 + 0) * 2 + 0];
                    ed[grow * 4 + h0]     = part[(tid * 2 + 0) * 2 + 1];
                    es[grow * 4 + h0 + 1] = part[(tid * 2 + 1) * 2 + 0];
                    ed[grow * 4 + h0 + 1] = part[(tid * 2 + 1) * 2 + 1];
                } else {
                    int h = col0 / 128;
                    es[grow * 4 + h] = part[(tid * 2 + 0) * 2 + 0] + part[(tid * 2 + 1) * 2 + 0];
                    ed[grow * 4 + h] = part[(tid * 2 + 0) * 2 + 1] + part[(tid * 2 + 1) * 2 + 1];
                }
            }
        }
    }
}

// ---------------- fused per-node GAT aggregation (fp16 gathers, fp32 accum) ---------
__device__ __forceinline__ float4 expleaky4(float4 a, float4 b) {
    float4 v;
    v.x = a.x + b.x; v.x = v.x > 0.f ? v.x : 0.2f * v.x; v.x = __expf(v.x);
    v.y = a.y + b.y; v.y = v.y > 0.f ? v.y : 0.2f * v.y; v.y = __expf(v.y);
    v.z = a.z + b.z; v.z = v.z > 0.f ? v.z : 0.2f * v.z; v.z = __expf(v.z);
    v.w = a.w + b.w; v.w = v.w > 0.f ? v.w : 0.2f * v.w; v.w = __expf(v.w);
    return v;
}

#define CHUNK 64

// Layer 1: out = hr stored fp16 (GEMM2 consumes fp16 A).
__global__ __launch_bounds__(128) void gat_agg1(
    const __half* __restrict__ h, const float* __restrict__ es, const float* __restrict__ ed,
    const float* __restrict__ bias, __half* __restrict__ out) {
    int n = blockIdx.x;
    int tid = threadIdx.x;
    int lane = tid & 31, wid = tid >> 5;
    int r0 = g_rowptr[n], r1 = g_rowptr[n + 1];
    int deg = r1 - r0;
    float4 edv = *reinterpret_cast<const float4*>(ed + n * 4);

    __shared__ float4 s_red[4];
    __shared__ int    s_src[CHUNK];
    __shared__ float4 s_w[CHUNK];

    const __half2* hp = reinterpret_cast<const __half2*>(h) + tid;

    float a0 = 0.f, a1 = 0.f;
    float4 dpart = make_float4(0.f, 0.f, 0.f, 0.f);
    for (int base = 0; base < deg; base += CHUNK) {
        int cn = deg - base; if (cn > CHUNK) cn = CHUNK;
        if (tid < cn) {
            int s = g_srcs[r0 + base + tid];
            float4 w = expleaky4(*reinterpret_cast<const float4*>(es + s * 4), edv);
            s_src[tid] = s;
            s_w[tid] = w;
            dpart.x += w.x; dpart.y += w.y; dpart.z += w.z; dpart.w += w.w;
        }
        __syncthreads();
        const float* wf = reinterpret_cast<const float*>(s_w);
        int j = 0;
        for (; j + 4 <= cn; j += 4) {
            int s0 = s_src[j + 0], s1 = s_src[j + 1];
            int s2 = s_src[j + 2], s3 = s_src[j + 3];
            float w0 = wf[(j + 0) * 4 + wid];
            float w1 = wf[(j + 1) * 4 + wid];
            float w2 = wf[(j + 2) * 4 + wid];
            float w3 = wf[(j + 3) * 4 + wid];
            float2 v0 = __half22float2(hp[(size_t)s0 * (F1 / 2)]);
            float2 v1 = __half22float2(hp[(size_t)s1 * (F1 / 2)]);
            float2 v2 = __half22float2(hp[(size_t)s2 * (F1 / 2)]);
            float2 v3 = __half22float2(hp[(size_t)s3 * (F1 / 2)]);
            a0 += w0 * v0.x; a1 += w0 * v0.y;
            a0 += w1 * v1.x; a1 += w1 * v1.y;
            a0 += w2 * v2.x; a1 += w2 * v2.y;
            a0 += w3 * v3.x; a1 += w3 * v3.y;
        }
        for (; j < cn; j++) {
            int s = s_src[j];
            float w = wf[j * 4 + wid];
            float2 hv = __half22float2(hp[(size_t)s * (F1 / 2)]);
            a0 += w * hv.x;
            a1 += w * hv.y;
        }
        __syncthreads();
    }
#pragma unroll
    for (int off = 16; off >= 1; off >>= 1) {
        dpart.x += __shfl_xor_sync(0xffffffffu, dpart.x, off);
        dpart.y += __shfl_xor_sync(0xffffffffu, dpart.y, off);
        dpart.z += __shfl_xor_sync(0xffffffffu, dpart.z, off);
        dpart.w += __shfl_xor_sync(0xffffffffu, dpart.w, off);
    }
    if (lane == 0) s_red[wid] = dpart;
    __syncthreads();
    float4 dt = s_red[0];
    dt.x += s_red[1].x + s_red[2].x + s_red[3].x;
    dt.y += s_red[1].y + s_red[2].y + s_red[3].y;
    dt.z += s_red[1].z + s_red[2].z + s_red[3].z;
    dt.w += s_red[1].w + s_red[2].w + s_red[3].w;
    float den = ((const float*)&dt)[wid] + 1e-16f;
    float inv = 1.f / den;
    int c = tid * 2;
    float o0 = a0 * inv + bias[c];
    float o1 = a1 * inv + bias[c + 1];
    o0 = o0 > 0.f ? o0 : 0.f;
    o1 = o1 > 0.f ? o1 : 0.f;
    *reinterpret_cast<__half2*>(out + (size_t)n * F1 + c) = __floats2half2_rn(o0, o1);
}

__global__ __launch_bounds__(128) void gat_agg2(
    const __half* __restrict__ h, const float* __restrict__ es, const float* __restrict__ ed,
    const float* __restrict__ bias, const float* __restrict__ gamma,
    const float* __restrict__ beta, float* __restrict__ out) {
    int n = blockIdx.x;
    int tid = threadIdx.x;
    int lane = tid & 31, wid = tid >> 5;
    int r0 = g_rowptr[n], r1 = g_rowptr[n + 1];
    int deg = r1 - r0;
    float4 edv = *reinterpret_cast<const float4*>(ed + n * 4);

    __shared__ float4 s_red[4];
    __shared__ int    s_src[CHUNK];
    __shared__ float4 s_w[CHUNK];
    __shared__ float  s_y[F2];
    __shared__ float  s_ln[4];

    const uint2* hp = reinterpret_cast<const uint2*>(h) + tid;

    float a0 = 0.f, a1 = 0.f, a2 = 0.f, a3 = 0.f;
    float4 dpart = make_float4(0.f, 0.f, 0.f, 0.f);
    for (int base = 0; base < deg; base += CHUNK) {
        int cn = deg - base; if (cn > CHUNK) cn = CHUNK;
        if (tid < cn) {
            int s = g_srcs[r0 + base + tid];
            float4 w = expleaky4(*reinterpret_cast<const float4*>(es + s * 4), edv);
            s_src[tid] = s;
            s_w[tid] = w;
            dpart.x += w.x; dpart.y += w.y; dpart.z += w.z; dpart.w += w.w;
        }
        __syncthreads();
        const float* wf = reinterpret_cast<const float*>(s_w);
        int j = 0;
        for (; j + 4 <= cn; j += 4) {
            int s0 = s_src[j + 0], s1 = s_src[j + 1];
            int s2 = s_src[j + 2], s3 = s_src[j + 3];
            float w0 = wf[(j + 0) * 4 + wid];
            float w1 = wf[(j + 1) * 4 + wid];
            float w2 = wf[(j + 2) * 4 + wid];
            float w3 = wf[(j + 3) * 4 + wid];
            uint2 r0v = hp[(size_t)s0 * (F2 / 4)];
            uint2 r1v = hp[(size_t)s1 * (F2 / 4)];
            uint2 r2v = hp[(size_t)s2 * (F2 / 4)];
            uint2 r3v = hp[(size_t)s3 * (F2 / 4)];
            float2 p0 = __half22float2(*reinterpret_cast<__half2*>(&r0v.x));
            float2 q0 = __half22float2(*reinterpret_cast<__half2*>(&r0v.y));
            float2 p1 = __half22float2(*reinterpret_cast<__half2*>(&r1v.x));
            float2 q1 = __half22float2(*reinterpret_cast<__half2*>(&r1v.y));
            float2 p2 = __half22float2(*reinterpret_cast<__half2*>(&r2v.x));
            float2 q2 = __half22float2(*reinterpret_cast<__half2*>(&r2v.y));
            float2 p3 = __half22float2(*reinterpret_cast<__half2*>(&r3v.x));
            float2 q3 = __half22float2(*reinterpret_cast<__half2*>(&r3v.y));
            a0 += w0 * p0.x; a1 += w0 * p0.y; a2 += w0 * q0.x; a3 += w0 * q0.y;
            a0 += w1 * p1.x; a1 += w1 * p1.y; a2 += w1 * q1.x; a3 += w1 * q1.y;
            a0 += w2 * p2.x; a1 += w2 * p2.y; a2 += w2 * q2.x; a3 += w2 * q2.y;
            a0 += w3 * p3.x; a1 += w3 * p3.y; a2 += w3 * q3.x; a3 += w3 * q3.y;
        }
        for (; j < cn; j++) {
            int s = s_src[j];
            float w = wf[j * 4 + wid];
            uint2 rv = hp[(size_t)s * (F2 / 4)];
            float2 p = __half22float2(*reinterpret_cast<__half2*>(&rv.x));
            float2 q = __half22float2(*reinterpret_cast<__half2*>(&rv.y));
            a0 += w * p.x; a1 += w * p.y; a2 += w * q.x; a3 += w * q.y;
        }
        __syncthreads();
    }
#pragma unroll
    for (int off = 16; off >= 1; off >>= 1) {
        dpart.x += __shfl_xor_sync(0xffffffffu, dpart.x, off);
        dpart.y += __shfl_xor_sync(0xffffffffu, dpart.y, off);
        dpart.z += __shfl_xor_sync(0xffffffffu, dpart.z, off);
        dpart.w += __shfl_xor_sync(0xffffffffu, dpart.w, off);
    }
    if (lane == 0) s_red[wid] = dpart;
    __syncthreads();
    float4 dt = s_red[0];
    dt.x += s_red[1].x + s_red[2].x + s_red[3].x;
    dt.y += s_red[1].y + s_red[2].y + s_red[3].y;
    dt.z += s_red[1].z + s_red[2].z + s_red[3].z;
    dt.w += s_red[1].w + s_red[2].w + s_red[3].w;
    float inv = 1.f / (((const float*)&dt)[wid] + 1e-16f);
    int l = tid * 4;
    s_y[l + 0] = a0 * inv;
    s_y[l + 1] = a1 * inv;
    s_y[l + 2] = a2 * inv;
    s_y[l + 3] = a3 * inv;
    __syncthreads();

    int c = tid;
    float y = 0.25f * (s_y[c] + s_y[128 + c] + s_y[256 + c] + s_y[384 + c]) + bias[c];
    float t = y;
#pragma unroll
    for (int off = 16; off >= 1; off >>= 1) t += __shfl_xor_sync(0xffffffffu, t, off);
    if (lane == 0) s_ln[wid] = t;
    __syncthreads();
    float mu = (s_ln[0] + s_ln[1] + s_ln[2] + s_ln[3]) * (1.f / 128.f);
    float dv = y - mu;
    t = dv * dv;
#pragma unroll
    for (int off = 16; off >= 1; off >>= 1) t += __shfl_xor_sync(0xffffffffu, t, off);
    __syncthreads();
    if (lane == 0) s_ln[wid] = t;
    __syncthreads();
    float var = (s_ln[0] + s_ln[1] + s_ln[2] + s_ln[3]) * (1.f / 128.f);
    out[(size_t)n * 128 + c] = dv * rsqrtf(var + 1e-5f) * gamma[c] + beta[c];
}

// ---------------- launch ----------------
extern "C" void kernel_launch(void* const* d_in, const int* in_sizes, int n_in,
                              void* d_out, int out_size) {
    const float* x     = (const float*)d_in[0];
    const void*  ei    = d_in[1];
    const float* W1    = (const float*)d_in[2];
    const float* as1   = (const float*)d_in[3];
    const float* ad1   = (const float*)d_in[4];
    const float* b1    = (const float*)d_in[5];
    const float* W2    = (const float*)d_in[6];
    const float* as2   = (const float*)d_in[7];
    const float* ad2   = (const float*)d_in[8];
    const float* b2    = (const float*)d_in[9];
    const float* gamma = (const float*)d_in[10];
    const float* beta  = (const float*)d_in[11];
    float*       out   = (float*)d_out;

    __half *p_h1, *p_hr, *p_h2, *p_xh, *p_w1t, *p_w2t;
    float *p_es, *p_ed;
    cudaGetSymbolAddress((void**)&p_h1,  g_h1);
    cudaGetSymbolAddress((void**)&p_hr,  g_hr);
    cudaGetSymbolAddress((void**)&p_h2,  g_h2);
    cudaGetSymbolAddress((void**)&p_xh,  g_xh);
    cudaGetSymbolAddress((void**)&p_w1t, g_w1t);
    cudaGetSymbolAddress((void**)&p_w2t, g_w2t);
    cudaGetSymbolAddress((void**)&p_es,  g_es);
    cudaGetSymbolAddress((void**)&p_ed,  g_ed);

    const int TB = 256;
    int rows128 = (NN + 127) / 128;             // 391
    int edgeBlocks = (ETOT + TB - 1) / TB;      // 3321

    // ---- CSR build + fp16 prep ----
    detect_idx_kernel<<<1, 32>>>((const int*)ei);
    zero_deg<<<(NN + TB - 1) / TB, TB>>>();
    hist_kernel<<<edgeBlocks, TB>>>(ei);
    scan_tiles<<<NT, 1024>>>();
    scan_parts<<<1, 64>>>();
    add_offsets<<<NT, 1024>>>();
    scatter_kernel<<<edgeBlocks, TB>>>(ei);
    f2h_copy<<<1024, TB>>>(x, p_xh, NN * 128 / 2);
    transpose_h<<<(128 * F1 + TB - 1) / TB, TB>>>(W1, p_w1t, 128, F1);
    transpose_h<<<(F1 * F2 + TB - 1) / TB, TB>>>(W2, p_w2t, F1, F2);

    // ---- layer 1 (fp16 GEMM, scores fused) ----
    gemm_h16<64><<<dim3(F1 / 128, rows128), 256>>>(
        p_xh, p_w1t, p_h1, NN, 128, F1, as1, ad1, p_es, p_ed);
    gat_agg1<<<NN, 128>>>(p_h1, p_es, p_ed, b1, p_hr);

    // ---- layer 2 (fp16 GEMM, scores fused) ----
    gemm_h16<128><<<dim3(F2 / 128, rows128), 256>>>(
        p_hr, p_w2t, p_h2, NN, 256, F2, as2, ad2, p_es, p_ed);
    gat_agg2<<<NN, 128>>>(p_h2, p_es, p_ed, b2, gamma, beta, out);
}